// round 6
// baseline (speedup 1.0000x reference)
#include <cuda_runtime.h>
#include <cuda_bf16.h>
#include <cstdint>

#define NE 8
#define DD 512
#define HH 2048
#define NTOK 4096
#define CAP 4096

#define QM 16256.0f   // 127*128: 15-bit quantization range

// ---------------- device scratch (static, allocation-free) ----------------
__device__ int      g_cnt[NE];
__device__ int      g_tok[NE * CAP];
__device__ float    g_w[NE * CAP];
__device__ float    g_xs[NTOK];                       // per-token x scale
__device__ int8_t   g_xd1[(size_t)NTOK * DD];
__device__ int8_t   g_xd2[(size_t)NTOK * DD];
__device__ uint32_t g_w1max[NE * HH];                 // per-n |W| max (bits)
__device__ uint32_t g_w2max[NE * DD];
__device__ int8_t   g_w1d1[(size_t)NE * HH * DD];     // [e][n][k] digits
__device__ int8_t   g_w1d2[(size_t)NE * HH * DD];
__device__ int8_t   g_w2d1[(size_t)NE * DD * HH];
__device__ int8_t   g_w2d2[(size_t)NE * DD * HH];
__device__ float    g_hf[(size_t)NE * CAP * HH];      // fc1 fp32 output
__device__ uint32_t g_hmax[NE * CAP];                 // per-slot-row h max (bits)
__device__ int8_t   g_hd1[(size_t)NE * CAP * HH];
__device__ int8_t   g_hd2[(size_t)NE * CAP * HH];

// ---------------- helpers ----------------
__device__ __forceinline__ uint32_t smem_u32(const void* p) {
    uint32_t a;
    asm("{ .reg .u64 t; cvta.to.shared.u64 t, %1; cvt.u32.u64 %0, t; }" : "=r"(a) : "l"(p));
    return a;
}
#define CP_ASYNC16(dst, src) \
    asm volatile("cp.async.cg.shared.global [%0], [%1], 16;" :: "r"(dst), "l"(src) : "memory")
#define CP_COMMIT() asm volatile("cp.async.commit_group;" ::: "memory")
#define CP_WAIT(n)  asm volatile("cp.async.wait_group %0;" :: "n"(n) : "memory")

__device__ __forceinline__ void ldsm4(uint32_t* r, uint32_t addr) {
    asm volatile("ldmatrix.sync.aligned.m8n8.x4.shared.b16 {%0,%1,%2,%3}, [%4];"
                 : "=r"(r[0]), "=r"(r[1]), "=r"(r[2]), "=r"(r[3]) : "r"(addr));
}
__device__ __forceinline__ void mma16832(int* c, const uint32_t* a, const uint32_t* b) {
    asm volatile(
        "mma.sync.aligned.m16n8k32.row.col.s32.s8.s8.s32 "
        "{%0,%1,%2,%3},{%4,%5,%6,%7},{%8,%9},{%0,%1,%2,%3};"
        : "+r"(c[0]), "+r"(c[1]), "+r"(c[2]), "+r"(c[3])
        : "r"(a[0]), "r"(a[1]), "r"(a[2]), "r"(a[3]), "r"(b[0]), "r"(b[1]));
}
// quantize v (|v| <= s) into two int8 digits: q = rn(v/s*QM) = 128*d1 + d2
__device__ __forceinline__ void quant2(float v, float inv, int8_t& d1, int8_t& d2) {
    int q = __float2int_rn(v * inv);
    int a1 = __float2int_rn((float)q * (1.0f / 128.0f));
    int a2 = q - (a1 << 7);
    d1 = (int8_t)a1; d2 = (int8_t)a2;
}

// SMEM tile geometry: 64B int8 rows (K-stage 64) padded to 80B
#define ROWB 80
#define TSZ  (128 * ROWB)
#define STAGEB (4 * TSZ)          // A1,A2,B1,B2
#define NST 5
#define SMEM_GEMM (NST * STAGEB)  // 204800

// ============================================================================
// Gate + fused x quantization (warp per token)
// ============================================================================
__global__ void gate_kernel(const float* __restrict__ x,
                            const float* __restrict__ Wg,
                            const float* __restrict__ bg,
                            float* __restrict__ gates_out) {
    __shared__ float sWg[DD * NE];
    for (int i = threadIdx.x; i < DD * NE; i += blockDim.x) sWg[i] = Wg[i];
    __syncthreads();

    const int warp = threadIdx.x >> 5;
    const int lane = threadIdx.x & 31;
    const int t = blockIdx.x * (blockDim.x >> 5) + warp;
    if (t >= NTOK) return;

    float acc[NE];
#pragma unroll
    for (int e = 0; e < NE; e++) acc[e] = 0.f;
    float xv[16];
    float mx = 0.f;
    const float* xr = x + (size_t)t * DD;
#pragma unroll
    for (int j = 0; j < 16; j++) {
        float v = xr[lane + 32 * j];
        xv[j] = v;
        mx = fmaxf(mx, fabsf(v));
#pragma unroll
        for (int e = 0; e < NE; e++) acc[e] = fmaf(v, sWg[(lane + 32 * j) * NE + e], acc[e]);
    }
#pragma unroll
    for (int off = 16; off; off >>= 1) {
        mx = fmaxf(mx, __shfl_xor_sync(0xffffffffu, mx, off));
#pragma unroll
        for (int e = 0; e < NE; e++) acc[e] += __shfl_xor_sync(0xffffffffu, acc[e], off);
    }

    // x quantization (all lanes)
    float s = fmaxf(mx, 1e-30f);
    float inv = QM / s;
    if (lane == 0) g_xs[t] = s;
#pragma unroll
    for (int j = 0; j < 16; j++) {
        int8_t d1, d2;
        quant2(xv[j], inv, d1, d2);
        g_xd1[(size_t)t * DD + 32 * j + lane] = d1;
        g_xd2[(size_t)t * DD + 32 * j + lane] = d2;
    }

    if (lane == 0) {
        float lg[NE];
        float m = -1e30f;
#pragma unroll
        for (int e = 0; e < NE; e++) { lg[e] = acc[e] + bg[e]; m = fmaxf(m, lg[e]); }
        float ssum = 0.f;
#pragma unroll
        for (int e = 0; e < NE; e++) { lg[e] = expf(lg[e] - m); ssum += lg[e]; }
        float invs = 1.f / ssum;
#pragma unroll
        for (int e = 0; e < NE; e++) lg[e] *= invs;
#pragma unroll
        for (int e = 0; e < NE; e++) gates_out[(size_t)t * NE + e] = lg[e];

        int i1 = 0; float v1 = lg[0];
#pragma unroll
        for (int e = 1; e < NE; e++) if (lg[e] > v1) { v1 = lg[e]; i1 = e; }
        int i2 = -1; float v2 = -1.f;
#pragma unroll
        for (int e = 0; e < NE; e++) if (e != i1 && lg[e] > v2) { v2 = lg[e]; i2 = e; }

        int p1 = atomicAdd(&g_cnt[i1], 1);
        g_tok[i1 * CAP + p1] = t; g_w[i1 * CAP + p1] = v1;
        int p2 = atomicAdd(&g_cnt[i2], 1);
        g_tok[i2 * CAP + p2] = t; g_w[i2 * CAP + p2] = v2;
    }
}

// ============================================================================
// Per-output-row |W| max:  W [e][K][N] -> maxbits[e][N]
// grid (N/256, K/KCH, NE), block 256
// ============================================================================
__global__ void wmax_kernel(const float* __restrict__ W, int which,
                            int K, int N, int KCH) {
    uint32_t* maxbits = which ? g_w2max : g_w1max;
    const int e = blockIdx.z;
    const int n = blockIdx.x * 256 + threadIdx.x;
    const int k0 = blockIdx.y * KCH;
    const float* base = W + (size_t)e * K * N + n;
    float m = 0.f;
    for (int k = 0; k < KCH; k += 4) {
        m = fmaxf(m, fabsf(base[(size_t)(k0 + k) * N]));
        m = fmaxf(m, fabsf(base[(size_t)(k0 + k + 1) * N]));
        m = fmaxf(m, fabsf(base[(size_t)(k0 + k + 2) * N]));
        m = fmaxf(m, fabsf(base[(size_t)(k0 + k + 3) * N]));
    }
    atomicMax(&maxbits[e * N + n], __float_as_uint(m));
}

// ============================================================================
// Weight transpose + int8 2-digit quantize: W [e][K][N] -> digits [e][N][K]
// (globals resolved in DEVICE code — passing __device__ symbols as kernel
//  args from host was R5's fatal bug)
// ============================================================================
__global__ void wquant_kernel(const float* __restrict__ W, int which, int K, int N) {
    __shared__ float t[32][33];
    int8_t*  d1g = which ? g_w2d1 : g_w1d1;
    int8_t*  d2g = which ? g_w2d2 : g_w1d2;
    const uint32_t* maxbits = which ? g_w2max : g_w1max;
    const int e = blockIdx.z;
    const int n0 = blockIdx.x * 32, k0 = blockIdx.y * 32;
    const int tx = threadIdx.x, ty = threadIdx.y;
    const float* We = W + (size_t)e * K * N;
#pragma unroll
    for (int j = 0; j < 32; j += 8)
        t[ty + j][tx] = We[(size_t)(k0 + ty + j) * N + n0 + tx];
    __syncthreads();
#pragma unroll
    for (int j = 0; j < 32; j += 8) {
        int n = n0 + ty + j;
        float s = __uint_as_float(maxbits[e * N + n]);
        float inv = QM / fmaxf(s, 1e-30f);
        int8_t d1, d2;
        quant2(t[tx][ty + j], inv, d1, d2);
        size_t o = (size_t)e * N * K + (size_t)n * K + k0 + tx;
        d1g[o] = d1;
        d2g[o] = d2;
    }
}

// ============================================================================
// h quantize: g_hf row + g_hmax -> digits. grid (CAP, NE), block 256
// ============================================================================
__global__ void hquant_kernel() {
    const int e = blockIdx.y;
    const int r = blockIdx.x;
    if (r >= g_cnt[e]) return;
    const size_t row = (size_t)e * CAP + r;
    float s = __uint_as_float(g_hmax[row]);
    float inv = QM / fmaxf(s, 1e-30f);
    const int k = threadIdx.x * 8;
    float4 v0 = *(const float4*)(g_hf + row * HH + k);
    float4 v1 = *(const float4*)(g_hf + row * HH + k + 4);
    int8_t a1[8], a2[8];
    quant2(v0.x, inv, a1[0], a2[0]); quant2(v0.y, inv, a1[1], a2[1]);
    quant2(v0.z, inv, a1[2], a2[2]); quant2(v0.w, inv, a1[3], a2[3]);
    quant2(v1.x, inv, a1[4], a2[4]); quant2(v1.y, inv, a1[5], a2[5]);
    quant2(v1.z, inv, a1[6], a2[6]); quant2(v1.w, inv, a1[7], a2[7]);
    *(uint2*)(g_hd1 + row * HH + k) = *(uint2*)a1;
    *(uint2*)(g_hd2 + row * HH + k) = *(uint2*)a2;
}

// ============================================================================
// Expert GEMM (int8 3-term Ozaki): C = A@B^T, exact S11 & Sx int32 sums
//   IS_FC1: A = x digits (K=512), B = w1 digits (N=2048), epi: +b1, relu,
//           write fp32 h + row-max atomic
//   else  : A = h digits (K=2048 in 4 k-slices), B = w2 digits (N=512),
//           epi: atomicAdd out += w*(y + b2[slice0])
// CTA 128x128, 8 warps (warp 32x64), 5-stage cp.async, K-stage 64
// ============================================================================
template<int KTOT, bool IS_FC1>
__global__ void __launch_bounds__(256, 1)
moe_gemm_i8(const float* __restrict__ bias_g, float* __restrict__ out) {
    extern __shared__ __align__(16) char smem[];
    const uint32_t sb = smem_u32(smem);
    const int e = IS_FC1 ? blockIdx.z : (blockIdx.z >> 2);
    const int kslice = IS_FC1 ? 0 : (blockIdx.z & 3);
    const int kbase = kslice * 512;
    const int cnt = g_cnt[e];
    const int m0 = blockIdx.x * 128;
    if (m0 >= cnt) return;
    const int n0 = blockIdx.y * 128;
    const int NN = IS_FC1 ? HH : DD;

    const int tid = threadIdx.x;
    const int lane = tid & 31;
    const int wid = tid >> 5;
    const int mbase = (wid >> 1) * 32;
    const int nbase = (wid & 1) * 64;

    __shared__ int   rows[128];
    __shared__ float ssa[128];
    __shared__ float ssb[128];
    __shared__ float sbias[128];
    if (tid < 128) {
        int r = m0 + tid; if (r >= cnt) r = cnt - 1;
        if (IS_FC1) {
            int tok = g_tok[e * CAP + r];
            rows[tid] = tok;
            ssa[tid] = g_xs[tok];
        } else {
            rows[tid] = e * CAP + r;
            ssa[tid] = fmaxf(__uint_as_float(g_hmax[e * CAP + r]), 1e-30f);
        }
        ssb[tid] = fmaxf(__uint_as_float(
            (IS_FC1 ? g_w1max : g_w2max)[e * NN + n0 + tid]), 1e-30f);
        sbias[tid] = bias_g[(size_t)e * NN + n0 + tid];
    }
    __syncthreads();

    const int8_t* A1g = IS_FC1 ? g_xd1 : g_hd1;
    const int8_t* A2g = IS_FC1 ? g_xd2 : g_hd2;
    const int8_t* B1g = (IS_FC1 ? g_w1d1 : g_w2d1) + (size_t)e * NN * KTOT;
    const int8_t* B2g = (IS_FC1 ? g_w1d2 : g_w2d2) + (size_t)e * NN * KTOT;

    const int lr = tid >> 2, lc = tid & 3;
    auto load_stage = [&](int s, int buf) {
        const int k0 = kbase + s * 64;
        const uint32_t sa = sb + buf * STAGEB;
#pragma unroll
        for (int it = 0; it < 2; it++) {
            int r = lr + it * 64;
            uint32_t d = sa + r * ROWB + lc * 16;
            size_t asrc = (size_t)rows[r] * KTOT + k0 + lc * 16;
            CP_ASYNC16(d,           A1g + asrc);
            CP_ASYNC16(d + TSZ,     A2g + asrc);
            size_t bsrc = (size_t)(n0 + r) * KTOT + k0 + lc * 16;
            CP_ASYNC16(d + 2 * TSZ, B1g + bsrc);
            CP_ASYNC16(d + 3 * TSZ, B2g + bsrc);
        }
        CP_COMMIT();
    };

    int acc1[2][8][4], acc2[2][8][4];
#pragma unroll
    for (int im = 0; im < 2; im++)
#pragma unroll
        for (int jn = 0; jn < 8; jn++)
#pragma unroll
            for (int q = 0; q < 4; q++) { acc1[im][jn][q] = 0; acc2[im][jn][q] = 0; }

    constexpr int S = 512 / 64;   // 8 K-stages per CTA (fc2 covers 512-K slice)
    static_assert(IS_FC1 ? (KTOT == 512) : (KTOT == 2048), "k config");
#pragma unroll
    for (int p = 0; p < NST - 1; p++) {
        if (p < S) load_stage(p, p);
        else       CP_COMMIT();
    }

    int buf = 0;
    for (int s = 0; s < S; s++) {
        CP_WAIT(NST - 2);
        __syncthreads();
        {
            int sn = s + NST - 1;
            if (sn < S) load_stage(sn, sn % NST);
            else        CP_COMMIT();
        }
        const uint32_t base = sb + buf * STAGEB;
#pragma unroll
        for (int ks = 0; ks < 2; ks++) {
            uint32_t a1[2][4], a2[2][4], b1[8][2], b2[8][2];
#pragma unroll
            for (int im = 0; im < 2; im++) {
                uint32_t row = mbase + im * 16 + (lane & 7) + ((lane >> 3) & 1) * 8;
                uint32_t addr = base + row * ROWB + ks * 32 + (lane >> 4) * 16;
                ldsm4(a1[im], addr);
                ldsm4(a2[im], addr + TSZ);
            }
#pragma unroll
            for (int jn = 0; jn < 4; jn++) {
                uint32_t rowb = nbase + jn * 16 + (lane & 7) + (lane >> 4) * 8;
                uint32_t addr = base + 2 * TSZ + rowb * ROWB + ks * 32 + ((lane >> 3) & 1) * 16;
                uint32_t t[4];
                ldsm4(t, addr);
                b1[jn * 2][0] = t[0]; b1[jn * 2][1] = t[1];
                b1[jn * 2 + 1][0] = t[2]; b1[jn * 2 + 1][1] = t[3];
                ldsm4(t, addr + TSZ);
                b2[jn * 2][0] = t[0]; b2[jn * 2][1] = t[1];
                b2[jn * 2 + 1][0] = t[2]; b2[jn * 2 + 1][1] = t[3];
            }
#pragma unroll
            for (int im = 0; im < 2; im++)
#pragma unroll
                for (int jn = 0; jn < 8; jn++) {
                    mma16832(acc1[im][jn], a1[im], b1[jn]);
                    mma16832(acc2[im][jn], a1[im], b2[jn]);
                    mma16832(acc2[im][jn], a2[im], b1[jn]);
                }
        }
        buf++; if (buf == NST) buf = 0;
    }

    // ---- epilogue:  C = sA*sB*(K1*S11 + K2*Sx) ----
    const float K1 = 16384.0f / (QM * QM);
    const float K2 = K1 * (1.0f / 128.0f);
#pragma unroll
    for (int im = 0; im < 2; im++) {
        const int rloc0 = mbase + im * 16 + (lane >> 2);
#pragma unroll
        for (int p = 0; p < 2; p++) {
            const int rloc = rloc0 + p * 8;
            const int grow = m0 + rloc;
            if (grow >= cnt) continue;
            const float sA = ssa[rloc];
            if (IS_FC1) {
                size_t hb = ((size_t)e * CAP + grow) * HH + n0;
                float mloc = 0.f;
#pragma unroll
                for (int jn = 0; jn < 8; jn++) {
                    int cc = nbase + jn * 8 + (lane & 3) * 2;
                    float sc1 = sA * ssb[cc], sc2 = sA * ssb[cc + 1];
                    float2 v;
                    v.x = fmaxf(sc1 * (K1 * (float)acc1[im][jn][2 * p]     + K2 * (float)acc2[im][jn][2 * p])     + sbias[cc],     0.f);
                    v.y = fmaxf(sc2 * (K1 * (float)acc1[im][jn][2 * p + 1] + K2 * (float)acc2[im][jn][2 * p + 1]) + sbias[cc + 1], 0.f);
                    mloc = fmaxf(mloc, fmaxf(v.x, v.y));
                    *(float2*)(g_hf + hb + cc) = v;
                }
                // row-max: reduce across the 4 lanes sharing this row
                mloc = fmaxf(mloc, __shfl_xor_sync(0xffffffffu, mloc, 1));
                mloc = fmaxf(mloc, __shfl_xor_sync(0xffffffffu, mloc, 2));
                if ((lane & 3) == 0)
                    atomicMax(&g_hmax[(size_t)e * CAP + grow], __float_as_uint(mloc));
            } else {
                float wv = g_w[e * CAP + grow];
                int tok = g_tok[e * CAP + grow];
                float* orow = out + (size_t)tok * DD + n0;
                float bs = (kslice == 0) ? 1.f : 0.f;
#pragma unroll
                for (int jn = 0; jn < 8; jn++) {
                    int cc = nbase + jn * 8 + (lane & 3) * 2;
                    float y0 = sA * ssb[cc]     * (K1 * (float)acc1[im][jn][2 * p]     + K2 * (float)acc2[im][jn][2 * p])     + bs * sbias[cc];
                    float y1 = sA * ssb[cc + 1] * (K1 * (float)acc1[im][jn][2 * p + 1] + K2 * (float)acc2[im][jn][2 * p + 1]) + bs * sbias[cc + 1];
                    atomicAdd(&orow[cc],     wv * y0);
                    atomicAdd(&orow[cc + 1], wv * y1);
                }
            }
        }
    }
}

// ============================================================================
// launch
// ============================================================================
extern "C" void kernel_launch(void* const* d_in, const int* in_sizes, int n_in,
                              void* d_out, int out_size) {
    const float* x  = (const float*)d_in[0];
    const float* Wg = (const float*)d_in[1];
    const float* bg = (const float*)d_in[2];
    const float* W1 = (const float*)d_in[3];
    const float* b1 = (const float*)d_in[4];
    const float* W2 = (const float*)d_in[5];
    const float* b2 = (const float*)d_in[6];
    float* out = (float*)d_out;

    void *cntp, *hmaxp, *w1maxp, *w2maxp;
    cudaGetSymbolAddress(&cntp, g_cnt);
    cudaGetSymbolAddress(&hmaxp, g_hmax);
    cudaGetSymbolAddress(&w1maxp, g_w1max);
    cudaGetSymbolAddress(&w2maxp, g_w2max);
    cudaMemsetAsync(cntp, 0, NE * sizeof(int));
    cudaMemsetAsync(hmaxp, 0, NE * CAP * sizeof(uint32_t));
    cudaMemsetAsync(w1maxp, 0, NE * HH * sizeof(uint32_t));
    cudaMemsetAsync(w2maxp, 0, NE * DD * sizeof(uint32_t));
    cudaMemsetAsync(out, 0, (size_t)NTOK * DD * sizeof(float));

    float* gates_out = out + (size_t)NTOK * DD;

    cudaFuncSetAttribute(moe_gemm_i8<DD, true>,  cudaFuncAttributeMaxDynamicSharedMemorySize, SMEM_GEMM);
    cudaFuncSetAttribute(moe_gemm_i8<HH, false>, cudaFuncAttributeMaxDynamicSharedMemorySize, SMEM_GEMM);

    gate_kernel<<<NTOK / 8, 256>>>(x, Wg, bg, gates_out);
    wmax_kernel<<<dim3(HH / 256, 2, NE), 256>>>(W1, 0, DD, HH, 256);
    wmax_kernel<<<dim3(DD / 256, 8, NE), 256>>>(W2, 1, HH, DD, 256);
    wquant_kernel<<<dim3(HH / 32, DD / 32, NE), dim3(32, 8)>>>(W1, 0, DD, HH);
    wquant_kernel<<<dim3(DD / 32, HH / 32, NE), dim3(32, 8)>>>(W2, 1, HH, DD);

    moe_gemm_i8<DD, true ><<<dim3(CAP / 128, HH / 128, NE), 256, SMEM_GEMM>>>(b1, nullptr);
    hquant_kernel<<<dim3(CAP, NE), 256>>>();
    moe_gemm_i8<HH, false><<<dim3(CAP / 128, DD / 128, NE * 4), 256, SMEM_GEMM>>>(b2, out);
}

// round 7
// speedup vs baseline: 2.6885x; 2.6885x over previous
#include <cuda_runtime.h>
#include <cuda_bf16.h>
#include <cstdint>

#define NE 8
#define DD 512
#define HH 2048
#define NTOK 4096
#define CAP 4096

// ---------------- device scratch (static, allocation-free) ----------------
__device__ int   g_cnt[NE];
__device__ int   g_tok[NE * CAP];
__device__ float g_w[NE * CAP];
__device__ __nv_bfloat16 g_x_hi[(size_t)NTOK * DD];
__device__ __nv_bfloat16 g_x_lo[(size_t)NTOK * DD];
__device__ __nv_bfloat16 g_h_hi[(size_t)NE * CAP * HH];
__device__ __nv_bfloat16 g_h_lo[(size_t)NE * CAP * HH];
__device__ __nv_bfloat16 g_w1t_hi[(size_t)NE * HH * DD];   // [e][n(H)][k(D)]
__device__ __nv_bfloat16 g_w1t_lo[(size_t)NE * HH * DD];
__device__ __nv_bfloat16 g_w2t_hi[(size_t)NE * DD * HH];   // [e][n(D)][k(H)]
__device__ __nv_bfloat16 g_w2t_lo[(size_t)NE * DD * HH];

// ---------------- helpers ----------------
__device__ __forceinline__ uint32_t smem_u32(const void* p) {
    uint32_t a;
    asm("{ .reg .u64 t; cvta.to.shared.u64 t, %1; cvt.u32.u64 %0, t; }" : "=r"(a) : "l"(p));
    return a;
}
#define CP_ASYNC16(dst, src) \
    asm volatile("cp.async.cg.shared.global [%0], [%1], 16;" :: "r"(dst), "l"(src) : "memory")
#define CP_COMMIT() asm volatile("cp.async.commit_group;" ::: "memory")
#define CP_WAIT(n)  asm volatile("cp.async.wait_group %0;" :: "n"(n) : "memory")

__device__ __forceinline__ void ldsm4(uint32_t* r, uint32_t addr) {
    asm volatile("ldmatrix.sync.aligned.m8n8.x4.shared.b16 {%0,%1,%2,%3}, [%4];"
                 : "=r"(r[0]), "=r"(r[1]), "=r"(r[2]), "=r"(r[3]) : "r"(addr));
}
__device__ __forceinline__ void mma16816(float* c, const uint32_t* a, const uint32_t* b) {
    asm volatile(
        "mma.sync.aligned.m16n8k16.row.col.f32.bf16.bf16.f32 "
        "{%0,%1,%2,%3},{%4,%5,%6,%7},{%8,%9},{%0,%1,%2,%3};"
        : "+f"(c[0]), "+f"(c[1]), "+f"(c[2]), "+f"(c[3])
        : "r"(a[0]), "r"(a[1]), "r"(a[2]), "r"(a[3]), "r"(b[0]), "r"(b[1]));
}
__device__ __forceinline__ void split2(float a, float b, uint32_t& hi, uint32_t& lo) {
    __nv_bfloat16 ha = __float2bfloat16(a), hb = __float2bfloat16(b);
    float la = a - __bfloat162float(ha);
    float lb = b - __bfloat162float(hb);
    __nv_bfloat162 H = __halves2bfloat162(ha, hb);
    __nv_bfloat162 L = __floats2bfloat162_rn(la, lb);
    hi = reinterpret_cast<uint32_t&>(H);
    lo = reinterpret_cast<uint32_t&>(L);
}

// SMEM tile geometry: rows of 32 bf16 (64B) padded to 80B (conflict-free ldmatrix)
#define ROWB 80
#define TSZ  (128 * ROWB)      // 10240 per tile (Ah/Al/Bh/Bl)
#define STAGEB (4 * TSZ)       // 40960 per stage
#define NST 2
#define SMEM_GEMM (NST * STAGEB)  // 81920  -> 2 CTAs/SM

// ============================================================================
// Gate
// ============================================================================
__global__ void gate_kernel(const float* __restrict__ x,
                            const float* __restrict__ Wg,
                            const float* __restrict__ bg,
                            float* __restrict__ gates_out) {
    __shared__ float sWg[DD * NE];
    for (int i = threadIdx.x; i < DD * NE; i += blockDim.x) sWg[i] = Wg[i];
    __syncthreads();

    const int warp = threadIdx.x >> 5;
    const int lane = threadIdx.x & 31;
    const int t = blockIdx.x * (blockDim.x >> 5) + warp;
    if (t >= NTOK) return;

    float acc[NE];
#pragma unroll
    for (int e = 0; e < NE; e++) acc[e] = 0.f;
    const float* xr = x + (size_t)t * DD;
    for (int d = lane; d < DD; d += 32) {
        float xv = xr[d];
#pragma unroll
        for (int e = 0; e < NE; e++) acc[e] = fmaf(xv, sWg[d * NE + e], acc[e]);
    }
#pragma unroll
    for (int off = 16; off; off >>= 1)
#pragma unroll
        for (int e = 0; e < NE; e++) acc[e] += __shfl_xor_sync(0xffffffffu, acc[e], off);

    if (lane == 0) {
        float lg[NE];
        float m = -1e30f;
#pragma unroll
        for (int e = 0; e < NE; e++) { lg[e] = acc[e] + bg[e]; m = fmaxf(m, lg[e]); }
        float s = 0.f;
#pragma unroll
        for (int e = 0; e < NE; e++) { lg[e] = expf(lg[e] - m); s += lg[e]; }
        float inv = 1.f / s;
#pragma unroll
        for (int e = 0; e < NE; e++) lg[e] *= inv;
#pragma unroll
        for (int e = 0; e < NE; e++) gates_out[(size_t)t * NE + e] = lg[e];

        int i1 = 0; float v1 = lg[0];
#pragma unroll
        for (int e = 1; e < NE; e++) if (lg[e] > v1) { v1 = lg[e]; i1 = e; }
        int i2 = -1; float v2 = -1.f;
#pragma unroll
        for (int e = 0; e < NE; e++) if (e != i1 && lg[e] > v2) { v2 = lg[e]; i2 = e; }

        int p1 = atomicAdd(&g_cnt[i1], 1);
        g_tok[i1 * CAP + p1] = t; g_w[i1 * CAP + p1] = v1;
        int p2 = atomicAdd(&g_cnt[i2], 1);
        g_tok[i2 * CAP + p2] = t; g_w[i2 * CAP + p2] = v2;
    }
}

// ============================================================================
// x split: fp32 -> bf16 hi/lo
// ============================================================================
__global__ void xsplit_kernel(const float* __restrict__ x) {
    const int i = blockIdx.x * blockDim.x + threadIdx.x;
    float4 v = ((const float4*)x)[i];
    uint32_t h0, l0, h1, l1;
    split2(v.x, v.y, h0, l0);
    split2(v.z, v.w, h1, l1);
    *(uint2*)(g_x_hi + (size_t)i * 4) = make_uint2(h0, h1);
    *(uint2*)(g_x_lo + (size_t)i * 4) = make_uint2(l0, l1);
}

// ============================================================================
// Weight transpose + split: W [e][K][N] fp32 -> [e][N][K] bf16 hi/lo
// ============================================================================
__global__ void wsplit_kernel(const float* __restrict__ W, int which, int K, int N) {
    __shared__ float t[32][33];
    const int e = blockIdx.z;
    const int n0 = blockIdx.x * 32, k0 = blockIdx.y * 32;
    const int tx = threadIdx.x, ty = threadIdx.y;
    const float* We = W + (size_t)e * K * N;
#pragma unroll
    for (int j = 0; j < 32; j += 8)
        t[ty + j][tx] = We[(size_t)(k0 + ty + j) * N + n0 + tx];
    __syncthreads();
    __nv_bfloat16* hi = (which ? g_w2t_hi : g_w1t_hi) + (size_t)e * K * N;
    __nv_bfloat16* lo = (which ? g_w2t_lo : g_w1t_lo) + (size_t)e * K * N;
#pragma unroll
    for (int j = 0; j < 32; j += 8) {
        float v = t[tx][ty + j];
        __nv_bfloat16 h = __float2bfloat16(v);
        float rem = v - __bfloat162float(h);
        size_t o = (size_t)(n0 + ty + j) * K + k0 + tx;
        hi[o] = h;
        lo[o] = __float2bfloat16(rem);
    }
}

// ============================================================================
// Expert GEMM: C = A @ B^T (+bias, epilogue), bf16 3-term split via mma.sync
//   IS_FC1: A = gathered g_x (K=512),  B = w1t (N=2048), epi = relu->split->g_h
//   else :  A = g_h slots   (K=2048),  B = w2t (N=512),  epi = atomicAdd out
// CTA 128x128, 8 warps (warp 32x64), double-buffer cp.async, 2 CTAs/SM
// ============================================================================
template<int KDIM, bool IS_FC1>
__global__ void __launch_bounds__(256, 2)
moe_gemm(const float* __restrict__ bias_g, float* __restrict__ out) {
    extern __shared__ __align__(16) char smem[];
    const uint32_t sb = smem_u32(smem);
    const int e = blockIdx.z;
    const int cnt = g_cnt[e];
    const int m0 = blockIdx.x * 128;
    if (m0 >= cnt) return;
    const int n0 = blockIdx.y * 128;
    const int NN = IS_FC1 ? HH : DD;

    const int tid = threadIdx.x;
    const int lane = tid & 31;
    const int wid = tid >> 5;
    const int mbase = (wid >> 1) * 32;   // 4 warps in M
    const int nbase = (wid & 1) * 64;    // 2 warps in N

    __shared__ int   rows[128];
    __shared__ float sbias[128];
    if (tid < 128) {
        int r = m0 + tid; if (r >= cnt) r = cnt - 1;
        rows[tid] = IS_FC1 ? g_tok[e * CAP + r] : (e * CAP + r);
        sbias[tid] = bias_g[(size_t)e * NN + n0 + tid];
    }
    __syncthreads();

    const __nv_bfloat16* Ah_g = IS_FC1 ? g_x_hi : g_h_hi;
    const __nv_bfloat16* Al_g = IS_FC1 ? g_x_lo : g_h_lo;
    const __nv_bfloat16* Bh_g = (IS_FC1 ? g_w1t_hi : g_w2t_hi) + (size_t)e * NN * KDIM;
    const __nv_bfloat16* Bl_g = (IS_FC1 ? g_w1t_lo : g_w2t_lo) + (size_t)e * NN * KDIM;

    const int lr = tid >> 2, lc = tid & 3;
    auto load_stage = [&](int s, int buf) {
        const int k0 = s * 32;
        const uint32_t sa = sb + buf * STAGEB;
#pragma unroll
        for (int it = 0; it < 2; it++) {
            int r = lr + it * 64;
            uint32_t d = sa + r * ROWB + lc * 16;
            size_t asrc = (size_t)rows[r] * KDIM + k0 + lc * 8;
            CP_ASYNC16(d,           Ah_g + asrc);
            CP_ASYNC16(d + TSZ,     Al_g + asrc);
            size_t bsrc = (size_t)(n0 + r) * KDIM + k0 + lc * 8;
            CP_ASYNC16(d + 2 * TSZ, Bh_g + bsrc);
            CP_ASYNC16(d + 3 * TSZ, Bl_g + bsrc);
        }
        CP_COMMIT();
    };

    float c[2][8][4];
#pragma unroll
    for (int im = 0; im < 2; im++)
#pragma unroll
        for (int jn = 0; jn < 8; jn++)
#pragma unroll
            for (int q = 0; q < 4; q++) c[im][jn][q] = 0.f;

    constexpr int S = KDIM / 32;
    load_stage(0, 0);

    for (int s = 0; s < S; s++) {
        CP_WAIT(0);              // stage s resident (stage s+1 not yet issued)
        __syncthreads();         // all warps done reading buf (s+1)&1
        if (s + 1 < S) load_stage(s + 1, (s + 1) & 1);
        const uint32_t base = sb + (s & 1) * STAGEB;
#pragma unroll
        for (int ks = 0; ks < 2; ks++) {
            uint32_t ah[2][4], al[2][4];
#pragma unroll
            for (int im = 0; im < 2; im++) {
                uint32_t row = mbase + im * 16 + (lane & 7) + ((lane >> 3) & 1) * 8;
                uint32_t addr = base + row * ROWB + (ks * 16 + (lane >> 4) * 8) * 2;
                ldsm4(ah[im], addr);
                ldsm4(al[im], addr + TSZ);
            }
            // process B in two groups of 4 jn (reduces live registers)
#pragma unroll
            for (int g = 0; g < 2; g++) {
                uint32_t bh[4][2], bl[4][2];
#pragma unroll
                for (int j2 = 0; j2 < 2; j2++) {
                    uint32_t rowb = nbase + g * 32 + j2 * 16 + (lane & 7) + (lane >> 4) * 8;
                    uint32_t addr = base + 2 * TSZ + rowb * ROWB + (ks * 16 + ((lane >> 3) & 1) * 8) * 2;
                    uint32_t t[4];
                    ldsm4(t, addr);
                    bh[j2 * 2][0] = t[0]; bh[j2 * 2][1] = t[1];
                    bh[j2 * 2 + 1][0] = t[2]; bh[j2 * 2 + 1][1] = t[3];
                    ldsm4(t, addr + TSZ);
                    bl[j2 * 2][0] = t[0]; bl[j2 * 2][1] = t[1];
                    bl[j2 * 2 + 1][0] = t[2]; bl[j2 * 2 + 1][1] = t[3];
                }
#pragma unroll
                for (int im = 0; im < 2; im++)
#pragma unroll
                    for (int j = 0; j < 4; j++) {
                        float* cc = c[im][g * 4 + j];
                        mma16816(cc, ah[im], bh[j]);
                        mma16816(cc, ah[im], bl[j]);
                        mma16816(cc, al[im], bh[j]);
                    }
            }
        }
        __syncthreads();
    }

    // ---- epilogue ----
#pragma unroll
    for (int im = 0; im < 2; im++) {
        const int rloc0 = mbase + im * 16 + (lane >> 2);
#pragma unroll
        for (int p = 0; p < 2; p++) {
            const int grow = m0 + rloc0 + p * 8;
            if (grow >= cnt) continue;
            if (IS_FC1) {
                size_t hb = ((size_t)e * CAP + grow) * HH;
#pragma unroll
                for (int jn = 0; jn < 8; jn++) {
                    int cc = nbase + jn * 8 + (lane & 3) * 2;
                    float v0 = fmaxf(c[im][jn][2 * p]     + sbias[cc],     0.f);
                    float v1 = fmaxf(c[im][jn][2 * p + 1] + sbias[cc + 1], 0.f);
                    uint32_t hi, lo;
                    split2(v0, v1, hi, lo);
                    *(uint32_t*)(g_h_hi + hb + n0 + cc) = hi;
                    *(uint32_t*)(g_h_lo + hb + n0 + cc) = lo;
                }
            } else {
                float wv = g_w[e * CAP + grow];
                int tok = g_tok[e * CAP + grow];
                float* orow = out + (size_t)tok * DD + n0;
#pragma unroll
                for (int jn = 0; jn < 8; jn++) {
                    int cc = nbase + jn * 8 + (lane & 3) * 2;
                    atomicAdd(&orow[cc],     (c[im][jn][2 * p]     + sbias[cc])     * wv);
                    atomicAdd(&orow[cc + 1], (c[im][jn][2 * p + 1] + sbias[cc + 1]) * wv);
                }
            }
        }
    }
}

// ============================================================================
// launch
// ============================================================================
extern "C" void kernel_launch(void* const* d_in, const int* in_sizes, int n_in,
                              void* d_out, int out_size) {
    const float* x  = (const float*)d_in[0];
    const float* Wg = (const float*)d_in[1];
    const float* bg = (const float*)d_in[2];
    const float* W1 = (const float*)d_in[3];
    const float* b1 = (const float*)d_in[4];
    const float* W2 = (const float*)d_in[5];
    const float* b2 = (const float*)d_in[6];
    float* out = (float*)d_out;

    void* cntp = nullptr;
    cudaGetSymbolAddress(&cntp, g_cnt);
    cudaMemsetAsync(cntp, 0, NE * sizeof(int));
    cudaMemsetAsync(out, 0, (size_t)NTOK * DD * sizeof(float));

    float* gates_out = out + (size_t)NTOK * DD;

    cudaFuncSetAttribute(moe_gemm<DD, true>,  cudaFuncAttributeMaxDynamicSharedMemorySize, SMEM_GEMM);
    cudaFuncSetAttribute(moe_gemm<HH, false>, cudaFuncAttributeMaxDynamicSharedMemorySize, SMEM_GEMM);

    gate_kernel<<<NTOK / 8, 256>>>(x, Wg, bg, gates_out);
    xsplit_kernel<<<NTOK * DD / 4 / 256, 256>>>(x);
    wsplit_kernel<<<dim3(HH / 32, DD / 32, NE), dim3(32, 8)>>>(W1, 0, DD, HH);
    wsplit_kernel<<<dim3(DD / 32, HH / 32, NE), dim3(32, 8)>>>(W2, 1, HH, DD);

    moe_gemm<DD, true ><<<dim3(CAP / 128, HH / 128, NE), 256, SMEM_GEMM>>>(b1, nullptr);
    moe_gemm<HH, false><<<dim3(CAP / 128, DD / 128, NE), 256, SMEM_GEMM>>>(b2, out);
}